// round 14
// baseline (speedup 1.0000x reference)
#include <cuda_runtime.h>
#include <cuda_bf16.h>
#include <math_constants.h>
#include <cstdint>

#define NROWS 16384
#define KCODES 8192
#define DIM 256
#define CAP 64
#define MT 64              // rows per CTA
#define TN 128             // codes per emb tile (s8: 128 x 256 B)
#define NT3 64             // 8192 / 128 tiles
#define EB 32768           // one s8 emb tile
#define ZQB 16384          // 64 rows x 256 B s8 z tile
#define SMEM_TOT (ZQB + 2 * EB + 1024)
// smem: [0,16K) z-s8 | [16K,48K) emb buf0 | [48K,80K) emb buf1 |
//       +0 scnt[64] | +256 thri[64] | +512 mint[64] | +768 mbarriers

// ---------------- static device scratch ----------------
__device__ __align__(16) signed char g_eq[KCODES * DIM];   // s8 emb, swizzled
__device__ int    g_cand[NROWS * CAP];
__device__ int    g_cidot[NROWS * CAP];
__device__ int    g_cnt[NROWS];
__device__ unsigned char g_over[NROWS];
__device__ int    g_thri[NROWS];
__device__ float  g_e2[KCODES];
__device__ int    g_emax_bits;    // max |e|  (monotone across replays)
__device__ int    g_sabse_bits;   // max over codes of sum |e|
__device__ double g_accum;

// ---------------- base-target PTX helpers ----------------
__device__ __forceinline__ uint32_t smem_u32(const void* p) {
    uint32_t a;
    asm("{ .reg .u64 t; cvta.to.shared.u64 t, %1; cvt.u32.u64 %0, t; }" : "=r"(a) : "l"(p));
    return a;
}
#define LDSM4(r, addr) \
    asm volatile("ldmatrix.sync.aligned.m8n8.x4.shared.b16 {%0,%1,%2,%3}, [%4];" \
                 : "=r"((r)[0]), "=r"((r)[1]), "=r"((r)[2]), "=r"((r)[3]) : "r"(addr))
#define MBARRIER_INIT(mb, c) \
    asm volatile("mbarrier.init.shared.b64 [%0], %1;" :: "r"((uint32_t)(mb)), "r"((uint32_t)(c)) : "memory")
#define MBARRIER_EXPECT_TX(mb, tx) \
    asm volatile("mbarrier.arrive.expect_tx.shared.b64 _, [%0], %1;" :: "r"((uint32_t)(mb)), "r"((uint32_t)(tx)) : "memory")
#define CPBULK(dst, src, bytes, mb) \
    asm volatile("cp.async.bulk.shared::cta.global.mbarrier::complete_tx::bytes [%0], [%1], %2, [%3];" \
                 :: "r"((uint32_t)(dst)), "l"(src), "r"((uint32_t)(bytes)), "r"((uint32_t)(mb)) : "memory")
#define MBARRIER_WAIT_PARITY(mb, par) do { \
    uint32_t _m = (uint32_t)(mb); uint32_t _p = (uint32_t)(par); uint32_t _d; \
    asm volatile("{\n\t.reg .pred p;\n\t" \
        "mbarrier.try_wait.parity.acquire.cta.shared::cta.b64 p, [%1], %2;\n\t" \
        "selp.b32 %0, 1, 0, p;\n\t}" : "=r"(_d) : "r"(_m), "r"(_p) : "memory"); \
    if (!_d) { \
        asm volatile("{\n\t.reg .pred P1;\n\tWL_%=:\n\t" \
            "mbarrier.try_wait.parity.acquire.cta.shared::cta.b64 P1, [%0], %1, 0x989680;\n\t" \
            "@P1 bra.uni WD_%=;\n\tbra.uni WL_%=;\n\tWD_%=:\n\t}" \
            :: "r"(_m), "r"(_p) : "memory"); \
    } } while (0)

__device__ __forceinline__ void imma16832(int* c, const uint32_t* a, uint32_t b0, uint32_t b1) {
    asm volatile(
        "mma.sync.aligned.m16n8k32.row.col.s32.s8.s8.s32 "
        "{%0,%1,%2,%3},{%4,%5,%6,%7},{%8,%9},{%0,%1,%2,%3};"
        : "+r"(c[0]), "+r"(c[1]), "+r"(c[2]), "+r"(c[3])
        : "r"(a[0]), "r"(a[1]), "r"(a[2]), "r"(a[3]), "r"(b0), "r"(b1));
}

__device__ __forceinline__ int q8(float v, float inv) {
    int i = __float2int_rn(v * inv);
    i = i > 127 ? 127 : (i < -127 ? -127 : i);
    return i & 0xFF;
}

// ---------------- emb stats: max|e|, max-row sum|e|, e2 ----------------
__global__ void emb_stat_kernel(const float* __restrict__ e) {
    if (blockIdx.x == 0 && threadIdx.x == 0) g_accum = 0.0;   // replay-safe
    int code = blockIdx.x * 8 + (threadIdx.x >> 5);
    int lane = threadIdx.x & 31;
    const float4* p = (const float4*)(e + (size_t)code * DIM);
    float s2 = 0.f, sa = 0.f, mx = 0.f;
#pragma unroll
    for (int j = 0; j < 2; j++) {
        float4 f = p[lane + 32 * j];
        s2 = __fmaf_rn(f.x, f.x, s2); s2 = __fmaf_rn(f.y, f.y, s2);
        s2 = __fmaf_rn(f.z, f.z, s2); s2 = __fmaf_rn(f.w, f.w, s2);
        sa += fabsf(f.x) + fabsf(f.y) + fabsf(f.z) + fabsf(f.w);
        mx = fmaxf(mx, fmaxf(fmaxf(fabsf(f.x), fabsf(f.y)), fmaxf(fabsf(f.z), fabsf(f.w))));
    }
#pragma unroll
    for (int o = 16; o; o >>= 1) {
        s2 += __shfl_xor_sync(0xffffffffu, s2, o);
        sa += __shfl_xor_sync(0xffffffffu, sa, o);
        mx = fmaxf(mx, __shfl_xor_sync(0xffffffffu, mx, o));
    }
    if (lane == 0) {
        g_e2[code] = s2;
        atomicMax(&g_emax_bits, __float_as_int(mx));
        atomicMax(&g_sabse_bits, __float_as_int(sa));
    }
}

// ---------------- emb quantize to s8 swizzled ----------------
__global__ void emb_quant_kernel(const float* __restrict__ e) {
    float inv = 127.0f / __int_as_float(g_emax_bits);
    size_t v4 = (size_t)blockIdx.x * 256 + threadIdx.x;   // one float4 -> 4 s8
    float4 f = ((const float4*)e)[v4];
    int code = (int)(v4 >> 6), u8 = (int)(v4 & 63);
    uint32_t packed = (uint32_t)(q8(f.x, inv) | (q8(f.y, inv) << 8) |
                                 (q8(f.z, inv) << 16) | (q8(f.w, inv) << 24));
    int chunk = u8 >> 2;                                   // 16B chunk 0..15
    uint32_t off = (uint32_t)code * 256 + (uint32_t)((chunk ^ (code & 7)) << 4) + (uint32_t)((u8 & 3) << 2);
    *(uint32_t*)((char*)g_eq + off) = packed;
}

// ---------------- phase 1: s8 IMMA GEMM + int-margin pruning ----------------
// 128 threads (4 warps); warp = (rg = w&1: rows rg*32..+31, nh = w>>1: code half)
__global__ __launch_bounds__(128, 2) void vq_mma(const float* __restrict__ z_e) {
    extern __shared__ char sm[];
    int* scnt  = (int*)(sm + ZQB + 2 * EB);
    int* thri  = scnt + 64;
    int* mints = thri + 64;
    const uint32_t sb = smem_u32(sm);
    const uint32_t bar0 = sb + ZQB + 2 * EB + 768, bar1 = bar0 + 8;
    const int tid = threadIdx.x, lane = tid & 31, w = tid >> 5;
    const int rg = w & 1, nh = w >> 1;
    const int n0 = blockIdx.x * MT;

    if (tid < MT) { scnt[tid] = 0; thri[tid] = -0x40000000; }
    if (tid == 0) { MBARRIER_INIT(bar0, 1); MBARRIER_INIT(bar1, 1); }
    __syncthreads();
    if (tid == 0) {
        MBARRIER_EXPECT_TX(bar0, EB);
        CPBULK(sb + ZQB, (const char*)g_eq, EB, bar0);
        MBARRIER_EXPECT_TX(bar1, EB);
        CPBULK(sb + ZQB + EB, (const char*)g_eq + EB, EB, bar1);
    }

    // z pass: warp w handles rows w*16..+15; per-row scale + quantize + margin
    const float se = __int_as_float(g_emax_bits) * (1.0f / 127.0f);
    const float sabse = __int_as_float(g_sabse_bits);
#pragma unroll 1
    for (int r16 = 0; r16 < 16; r16++) {
        int row = w * 16 + r16;
        const float4* zr = (const float4*)(z_e + (size_t)(n0 + row) * DIM);
        float4 f0 = zr[lane * 2], f1 = zr[lane * 2 + 1];
        float mx = fmaxf(fmaxf(fabsf(f0.x), fabsf(f0.y)), fmaxf(fabsf(f0.z), fabsf(f0.w)));
        mx = fmaxf(mx, fmaxf(fmaxf(fabsf(f1.x), fabsf(f1.y)), fmaxf(fabsf(f1.z), fabsf(f1.w))));
        float sa = fabsf(f0.x) + fabsf(f0.y) + fabsf(f0.z) + fabsf(f0.w)
                 + fabsf(f1.x) + fabsf(f1.y) + fabsf(f1.z) + fabsf(f1.w);
#pragma unroll
        for (int o = 16; o; o >>= 1) {
            mx = fmaxf(mx, __shfl_xor_sync(0xffffffffu, mx, o));
            sa += __shfl_xor_sync(0xffffffffu, sa, o);
        }
        float zmax = fmaxf(mx, 1e-20f);
        float sz = zmax * (1.0f / 127.0f);
        float inv = 127.0f / zmax;
        uint2 u;
        u.x = (uint32_t)(q8(f0.x, inv) | (q8(f0.y, inv) << 8) | (q8(f0.z, inv) << 16) | (q8(f0.w, inv) << 24));
        u.y = (uint32_t)(q8(f1.x, inv) | (q8(f1.y, inv) << 8) | (q8(f1.z, inv) << 16) | (q8(f1.w, inv) << 24));
        *(uint2*)(sm + row * 256 + (((lane >> 1) ^ (row & 7)) << 4) + (lane & 1) * 8) = u;
        if (lane == 0) {
            float mfp = se * sa + sz * sabse + 128.f * sz * se + 2.0e-4f;
            float q = mfp / (sz * se);
            mints[row] = (q > 5.0e8f) ? 0x1fffffff : ((int)q + 4);
        }
    }
    __syncthreads();

    // persistent A: rows rg*32..+31 (2 m16 groups), full K (8 k32-steps)
    uint32_t a[2][8][4];
#pragma unroll
    for (int mg = 0; mg < 2; mg++) {
        int row = rg * 32 + mg * 16 + (lane & 7) + ((lane >> 3) & 1) * 8;
#pragma unroll
        for (int ks = 0; ks < 8; ks++) {
            int chunk = 2 * ks + (lane >> 4);
            LDSM4(a[mg][ks], sb + (uint32_t)row * 256 + (uint32_t)((chunk ^ (row & 7)) << 4));
        }
    }

    // per-lane pruning state: 4 row-slots: slot = mg*2 + h -> row rg*32+mg*16+(lane>>2)+h*8
    int rmax[4], mint_l[4];
#pragma unroll
    for (int s = 0; s < 4; s++) {
        int rl = rg * 32 + (s >> 1) * 16 + (lane >> 2) + (s & 1) * 8;
        mint_l[s] = mints[rl];
        rmax[s] = -0x20000000;
    }

    for (int t = 0; t < NT3; t++) {
        MBARRIER_WAIT_PARITY(t & 1 ? bar1 : bar0, (t >> 1) & 1);
        const uint32_t eB = sb + ZQB + (uint32_t)(t & 1) * EB;

        int C[2][8][4];
#pragma unroll
        for (int i = 0; i < 2; i++)
#pragma unroll
            for (int j = 0; j < 8; j++)
#pragma unroll
                for (int k = 0; k < 4; k++) C[i][j][k] = 0;

        // B addresses: this warp's 64 codes = nh*64 + cgb*16 blocks
        uint32_t bbase[4];
#pragma unroll
        for (int cgb = 0; cgb < 4; cgb++) {
            int code = nh * 64 + cgb * 16 + (lane & 7) + ((lane >> 3) & 1) * 8;
            bbase[cgb] = eB + (uint32_t)code * 256 + (uint32_t)(((code & 7) << 4));  // chunk XOR applied per-ks below
        }
        // Note: swizzled chunk = (chunk ^ (code&7)); we fold code&7 via XOR each step.
        int codesw[4];
#pragma unroll
        for (int cgb = 0; cgb < 4; cgb++) {
            int code = nh * 64 + cgb * 16 + (lane & 7) + ((lane >> 3) & 1) * 8;
            codesw[cgb] = code & 7;
            bbase[cgb] = eB + (uint32_t)code * 256;
        }

        uint32_t b[2][4][4];
#pragma unroll
        for (int cgb = 0; cgb < 4; cgb++) {
            int chunk = 0 + (lane >> 4);
            LDSM4(b[0][cgb], bbase[cgb] + (uint32_t)((chunk ^ codesw[cgb]) << 4));
        }
#pragma unroll
        for (int ks = 0; ks < 8; ks++) {
            const int cur = ks & 1, nxt = cur ^ 1;
            if (ks < 7) {
                int chunk = 2 * (ks + 1) + (lane >> 4);
#pragma unroll
                for (int cgb = 0; cgb < 4; cgb++)
                    LDSM4(b[nxt][cgb], bbase[cgb] + (uint32_t)((chunk ^ codesw[cgb]) << 4));
            }
#pragma unroll
            for (int mg = 0; mg < 2; mg++)
#pragma unroll
                for (int cgb = 0; cgb < 4; cgb++) {
                    imma16832(C[mg][cgb * 2 + 0], a[mg][ks], b[cur][cgb][0], b[cur][cgb][2]);
                    imma16832(C[mg][cgb * 2 + 1], a[mg][ks], b[cur][cgb][1], b[cur][cgb][3]);
                }
        }

        // epilogue: integer capture, exact compares
#pragma unroll
        for (int mg = 0; mg < 2; mg++)
#pragma unroll
            for (int cg = 0; cg < 8; cg++) {
                int kbase = t * TN + nh * 64 + (cg >> 1) * 16 + (cg & 1) * 8 + (lane & 3) * 2;
#pragma unroll
                for (int c = 0; c < 4; c++) {
                    int d = C[mg][cg][c];
                    int s = mg * 2 + (c >> 1);
                    if (d >= rmax[s] - mint_l[s]) {
                        int rl = rg * 32 + (s >> 1) * 16 + (lane >> 2) + (s & 1) * 8;
                        int idx = atomicAdd(&scnt[rl], 1);
                        if (idx < CAP) {
                            g_cand[(size_t)(n0 + rl) * CAP + idx] = kbase + (c & 1);
                            g_cidot[(size_t)(n0 + rl) * CAP + idx] = d;
                        }
                        if (d > rmax[s]) rmax[s] = d;
                    }
                }
            }
        // share running max across the 4 owner lanes
#pragma unroll
        for (int s = 0; s < 4; s++) {
            int m = rmax[s];
            m = max(m, __shfl_xor_sync(0xffffffffu, m, 1));
            m = max(m, __shfl_xor_sync(0xffffffffu, m, 2));
            rmax[s] = m;
        }

        __syncthreads();
        if (tid == 0 && t + 2 < NT3) {
            uint32_t mb = (t & 1) ? bar1 : bar0;
            MBARRIER_EXPECT_TX(mb, EB);
            CPBULK(sb + ZQB + (uint32_t)(t & 1) * EB,
                   (const char*)g_eq + (size_t)(t + 2) * EB, EB, mb);
        }
    }

    // combine thresholds across the two code-half warps
    if ((lane & 3) == 0) {
#pragma unroll
        for (int s = 0; s < 4; s++) {
            int rl = rg * 32 + (s >> 1) * 16 + (lane >> 2) + (s & 1) * 8;
            atomicMax(&thri[rl], rmax[s] - mint_l[s]);
        }
    }
    __syncthreads();
    if (tid < MT) {
        int c = scnt[tid];
        g_cnt[n0 + tid] = c < CAP ? c : CAP;
        g_over[n0 + tid] = (c > CAP) ? 1 : 0;
        g_thri[n0 + tid] = thri[tid];
    }
}

// ---------------- phase 2: exact fp32 rescoring (int-threshold filtered) ----
__global__ void vq_exact(const float* __restrict__ z_e, const float* __restrict__ emb,
                         float* __restrict__ out) {
    __shared__ float zrow[8][DIM];
    int wid = threadIdx.x >> 5, lane = threadIdx.x & 31;
    int row = blockIdx.x * 8 + wid;
    {
        const float4* gz = (const float4*)(z_e + (size_t)row * DIM);
#pragma unroll
        for (int i = 0; i < 2; i++) {
            float4 v = gz[lane + 32 * i];
            *(float4*)&zrow[wid][4 * (lane + 32 * i)] = v;
        }
    }
    __syncwarp();
    const float* zr = zrow[wid];
    float x2 = 0.f;
    for (int d = 0; d < DIM; d++) x2 = __fmaf_rn(zr[d], zr[d], x2);

    float bt = CUDART_INF_F;
    int bk = 0x7fffffff;
    int cnt = g_cnt[row];
    bool over = g_over[row] != 0;
    int thrf = g_thri[row];
    int total = over ? KCODES : cnt;
    for (int c = lane; c < total; c += 32) {
        int k;
        if (over) k = c;
        else {
            if (g_cidot[(size_t)row * CAP + c] < thrf) continue;   // prefix junk
            k = g_cand[(size_t)row * CAP + c];
        }
        const float4* er = (const float4*)(emb + (size_t)k * DIM);
        float dot = 0.f;
#pragma unroll 8
        for (int q = 0; q < DIM / 4; q++) {
            float4 e4 = er[q];
            dot = __fmaf_rn(zr[4 * q + 0], e4.x, dot);
            dot = __fmaf_rn(zr[4 * q + 1], e4.y, dot);
            dot = __fmaf_rn(zr[4 * q + 2], e4.z, dot);
            dot = __fmaf_rn(zr[4 * q + 3], e4.w, dot);
        }
        float S = __fadd_rn(x2, g_e2[k]);
        float tt = __fadd_rn(S, -2.0f * dot);
        if (tt < bt || (tt == bt && k < bk)) { bt = tt; bk = k; }
    }
#pragma unroll
    for (int o = 16; o; o >>= 1) {
        float to = __shfl_down_sync(0xffffffffu, bt, o);
        int ko = __shfl_down_sync(0xffffffffu, bk, o);
        if (to < bt || (to == bt && ko < bk)) { bt = to; bk = ko; }
    }
    bk = __shfl_sync(0xffffffffu, bk, 0);

    // fused gather: z_q_st + loss partial + code output
    const float4* er = (const float4*)(emb + (size_t)bk * DIM);
    float4* po = (float4*)(out + (size_t)row * DIM);
    float sq = 0.f;
#pragma unroll
    for (int j = 0; j < 2; j++) {
        int q = lane + 32 * j;
        float4 e4 = er[q];
        const float* zp = &zrow[wid][4 * q];
        float4 o4;
        float d0 = __fsub_rn(e4.x, zp[0]); o4.x = __fadd_rn(zp[0], d0); sq = __fmaf_rn(d0, d0, sq);
        float d1 = __fsub_rn(e4.y, zp[1]); o4.y = __fadd_rn(zp[1], d1); sq = __fmaf_rn(d1, d1, sq);
        float d2 = __fsub_rn(e4.z, zp[2]); o4.z = __fadd_rn(zp[2], d2); sq = __fmaf_rn(d2, d2, sq);
        float d3 = __fsub_rn(e4.w, zp[3]); o4.w = __fadd_rn(zp[3], d3); sq = __fmaf_rn(d3, d3, sq);
        po[q] = o4;
    }
#pragma unroll
    for (int o = 16; o; o >>= 1) sq += __shfl_down_sync(0xffffffffu, sq, o);
    if (lane == 0) {
        atomicAdd(&g_accum, (double)sq);
        out[(size_t)NROWS * DIM + 1 + row] = (float)bk;
    }
}

__global__ void vq_loss(float* __restrict__ out) {
    float m = (float)(g_accum / (double)((size_t)NROWS * DIM));
    out[(size_t)NROWS * DIM] = __fadd_rn(m, 0.25f * m);
}

// ---------------------------------------------------------------------------
extern "C" void kernel_launch(void* const* d_in, const int* in_sizes, int n_in,
                              void* d_out, int out_size) {
    const float* z_e = (const float*)d_in[0];
    const float* emb = (const float*)d_in[1];
    if (n_in >= 2 && in_sizes[0] == KCODES * DIM && in_sizes[1] == NROWS * DIM) {
        const float* t = z_e; z_e = emb; emb = t;
    }
    float* out = (float*)d_out;

    cudaFuncSetAttribute(vq_mma, cudaFuncAttributeMaxDynamicSharedMemorySize, SMEM_TOT);

    emb_stat_kernel<<<KCODES / 8, 256>>>(emb);
    emb_quant_kernel<<<KCODES * DIM / 4 / 256, 256>>>(emb);
    vq_mma<<<NROWS / MT, 128, SMEM_TOT>>>(z_e);
    vq_exact<<<NROWS / 8, 256>>>(z_e, emb, out);
    vq_loss<<<1, 1>>>(out);
}

// round 17
// speedup vs baseline: 13.7471x; 13.7471x over previous
#include <cuda_runtime.h>
#include <cuda_bf16.h>
#include <math_constants.h>
#include <cstdint>

#define NROWS 16384
#define KCODES 8192
#define DIM 256
#define CAP 192            // s8 margin ~0.87 sigma captures 50-120/row; 64 overflowed
#define MT 64              // rows per CTA
#define TN 128             // codes per emb tile (s8: 128 x 256 B)
#define NT3 64             // 8192 / 128 tiles
#define EB 32768           // one s8 emb tile
#define ZQB 16384          // 64 rows x 256 B s8 z tile
#define SMEM_TOT (ZQB + 2 * EB + 1024)
// smem: [0,16K) z-s8 | [16K,48K) emb buf0 | [48K,80K) emb buf1 |
//       +0 scnt[64] | +256 thri[64] | +512 mint[64] | +768 mbarriers

// ---------------- static device scratch ----------------
__device__ __align__(16) signed char g_eq[KCODES * DIM];   // s8 emb, swizzled
__device__ int    g_cand[NROWS * CAP];
__device__ int    g_cidot[NROWS * CAP];
__device__ int    g_cnt[NROWS];
__device__ unsigned char g_over[NROWS];
__device__ int    g_thri[NROWS];
__device__ float  g_e2[KCODES];
__device__ int    g_emax_bits;    // max |e|  (monotone across replays)
__device__ int    g_sabse_bits;   // max over codes of sum |e|
__device__ double g_accum;

// ---------------- base-target PTX helpers ----------------
__device__ __forceinline__ uint32_t smem_u32(const void* p) {
    uint32_t a;
    asm("{ .reg .u64 t; cvta.to.shared.u64 t, %1; cvt.u32.u64 %0, t; }" : "=r"(a) : "l"(p));
    return a;
}
#define LDSM4(r, addr) \
    asm volatile("ldmatrix.sync.aligned.m8n8.x4.shared.b16 {%0,%1,%2,%3}, [%4];" \
                 : "=r"((r)[0]), "=r"((r)[1]), "=r"((r)[2]), "=r"((r)[3]) : "r"(addr))
#define MBARRIER_INIT(mb, c) \
    asm volatile("mbarrier.init.shared.b64 [%0], %1;" :: "r"((uint32_t)(mb)), "r"((uint32_t)(c)) : "memory")
#define MBARRIER_EXPECT_TX(mb, tx) \
    asm volatile("mbarrier.arrive.expect_tx.shared.b64 _, [%0], %1;" :: "r"((uint32_t)(mb)), "r"((uint32_t)(tx)) : "memory")
#define CPBULK(dst, src, bytes, mb) \
    asm volatile("cp.async.bulk.shared::cta.global.mbarrier::complete_tx::bytes [%0], [%1], %2, [%3];" \
                 :: "r"((uint32_t)(dst)), "l"(src), "r"((uint32_t)(bytes)), "r"((uint32_t)(mb)) : "memory")
#define MBARRIER_WAIT_PARITY(mb, par) do { \
    uint32_t _m = (uint32_t)(mb); uint32_t _p = (uint32_t)(par); uint32_t _d; \
    asm volatile("{\n\t.reg .pred p;\n\t" \
        "mbarrier.try_wait.parity.acquire.cta.shared::cta.b64 p, [%1], %2;\n\t" \
        "selp.b32 %0, 1, 0, p;\n\t}" : "=r"(_d) : "r"(_m), "r"(_p) : "memory"); \
    if (!_d) { \
        asm volatile("{\n\t.reg .pred P1;\n\tWL_%=:\n\t" \
            "mbarrier.try_wait.parity.acquire.cta.shared::cta.b64 P1, [%0], %1, 0x989680;\n\t" \
            "@P1 bra.uni WD_%=;\n\tbra.uni WL_%=;\n\tWD_%=:\n\t}" \
            :: "r"(_m), "r"(_p) : "memory"); \
    } } while (0)

__device__ __forceinline__ void imma16832(int* c, const uint32_t* a, uint32_t b0, uint32_t b1) {
    asm volatile(
        "mma.sync.aligned.m16n8k32.row.col.s32.s8.s8.s32 "
        "{%0,%1,%2,%3},{%4,%5,%6,%7},{%8,%9},{%0,%1,%2,%3};"
        : "+r"(c[0]), "+r"(c[1]), "+r"(c[2]), "+r"(c[3])
        : "r"(a[0]), "r"(a[1]), "r"(a[2]), "r"(a[3]), "r"(b0), "r"(b1));
}

__device__ __forceinline__ int q8(float v, float inv) {
    int i = __float2int_rn(v * inv);
    i = i > 127 ? 127 : (i < -127 ? -127 : i);
    return i & 0xFF;
}

// ---------------- emb stats: max|e|, max-row sum|e|, e2 ----------------
__global__ void emb_stat_kernel(const float* __restrict__ e) {
    if (blockIdx.x == 0 && threadIdx.x == 0) g_accum = 0.0;   // replay-safe
    int code = blockIdx.x * 8 + (threadIdx.x >> 5);
    int lane = threadIdx.x & 31;
    const float4* p = (const float4*)(e + (size_t)code * DIM);
    float s2 = 0.f, sa = 0.f, mx = 0.f;
#pragma unroll
    for (int j = 0; j < 2; j++) {
        float4 f = p[lane + 32 * j];
        s2 = __fmaf_rn(f.x, f.x, s2); s2 = __fmaf_rn(f.y, f.y, s2);
        s2 = __fmaf_rn(f.z, f.z, s2); s2 = __fmaf_rn(f.w, f.w, s2);
        sa += fabsf(f.x) + fabsf(f.y) + fabsf(f.z) + fabsf(f.w);
        mx = fmaxf(mx, fmaxf(fmaxf(fabsf(f.x), fabsf(f.y)), fmaxf(fabsf(f.z), fabsf(f.w))));
    }
#pragma unroll
    for (int o = 16; o; o >>= 1) {
        s2 += __shfl_xor_sync(0xffffffffu, s2, o);
        sa += __shfl_xor_sync(0xffffffffu, sa, o);
        mx = fmaxf(mx, __shfl_xor_sync(0xffffffffu, mx, o));
    }
    if (lane == 0) {
        g_e2[code] = s2;
        atomicMax(&g_emax_bits, __float_as_int(mx));
        atomicMax(&g_sabse_bits, __float_as_int(sa));
    }
}

// ---------------- emb quantize to s8 swizzled ----------------
__global__ void emb_quant_kernel(const float* __restrict__ e) {
    float inv = 127.0f / __int_as_float(g_emax_bits);
    size_t v4 = (size_t)blockIdx.x * 256 + threadIdx.x;   // one float4 -> 4 s8
    float4 f = ((const float4*)e)[v4];
    int code = (int)(v4 >> 6), u8 = (int)(v4 & 63);
    uint32_t packed = (uint32_t)(q8(f.x, inv) | (q8(f.y, inv) << 8) |
                                 (q8(f.z, inv) << 16) | (q8(f.w, inv) << 24));
    int chunk = u8 >> 2;                                   // 16B chunk 0..15
    uint32_t off = (uint32_t)code * 256 + (uint32_t)((chunk ^ (code & 7)) << 4) + (uint32_t)((u8 & 3) << 2);
    *(uint32_t*)((char*)g_eq + off) = packed;
}

// ---------------- phase 1: s8 IMMA GEMM + int-margin pruning ----------------
// 128 threads (4 warps); warp = (rg = w&1: rows rg*32..+31, nh = w>>1: code half)
__global__ __launch_bounds__(128, 2) void vq_mma(const float* __restrict__ z_e) {
    extern __shared__ char sm[];
    int* scnt  = (int*)(sm + ZQB + 2 * EB);
    int* thri  = scnt + 64;
    int* mints = thri + 64;
    const uint32_t sb = smem_u32(sm);
    const uint32_t bar0 = sb + ZQB + 2 * EB + 768, bar1 = bar0 + 8;
    const int tid = threadIdx.x, lane = tid & 31, w = tid >> 5;
    const int rg = w & 1, nh = w >> 1;
    const int n0 = blockIdx.x * MT;

    if (tid < MT) { scnt[tid] = 0; thri[tid] = -0x40000000; }
    if (tid == 0) { MBARRIER_INIT(bar0, 1); MBARRIER_INIT(bar1, 1); }
    __syncthreads();
    if (tid == 0) {
        MBARRIER_EXPECT_TX(bar0, EB);
        CPBULK(sb + ZQB, (const char*)g_eq, EB, bar0);
        MBARRIER_EXPECT_TX(bar1, EB);
        CPBULK(sb + ZQB + EB, (const char*)g_eq + EB, EB, bar1);
    }

    // z pass: warp w handles rows w*16..+15; per-row scale + quantize + margin
    const float se = __int_as_float(g_emax_bits) * (1.0f / 127.0f);
    const float sabse = __int_as_float(g_sabse_bits);
#pragma unroll 1
    for (int r16 = 0; r16 < 16; r16++) {
        int row = w * 16 + r16;
        const float4* zr = (const float4*)(z_e + (size_t)(n0 + row) * DIM);
        float4 f0 = zr[lane * 2], f1 = zr[lane * 2 + 1];
        float mx = fmaxf(fmaxf(fabsf(f0.x), fabsf(f0.y)), fmaxf(fabsf(f0.z), fabsf(f0.w)));
        mx = fmaxf(mx, fmaxf(fmaxf(fabsf(f1.x), fabsf(f1.y)), fmaxf(fabsf(f1.z), fabsf(f1.w))));
        float sa = fabsf(f0.x) + fabsf(f0.y) + fabsf(f0.z) + fabsf(f0.w)
                 + fabsf(f1.x) + fabsf(f1.y) + fabsf(f1.z) + fabsf(f1.w);
#pragma unroll
        for (int o = 16; o; o >>= 1) {
            mx = fmaxf(mx, __shfl_xor_sync(0xffffffffu, mx, o));
            sa += __shfl_xor_sync(0xffffffffu, sa, o);
        }
        float zmax = fmaxf(mx, 1e-20f);
        float sz = zmax * (1.0f / 127.0f);
        float inv = 127.0f / zmax;
        uint2 u;
        u.x = (uint32_t)(q8(f0.x, inv) | (q8(f0.y, inv) << 8) | (q8(f0.z, inv) << 16) | (q8(f0.w, inv) << 24));
        u.y = (uint32_t)(q8(f1.x, inv) | (q8(f1.y, inv) << 8) | (q8(f1.z, inv) << 16) | (q8(f1.w, inv) << 24));
        *(uint2*)(sm + row * 256 + (((lane >> 1) ^ (row & 7)) << 4) + (lane & 1) * 8) = u;
        if (lane == 0) {
            float mfp = se * sa + sz * sabse + 128.f * sz * se + 2.0e-4f;
            float q = mfp / (sz * se);
            mints[row] = (q > 5.0e8f) ? 0x1fffffff : ((int)q + 4);
        }
    }
    __syncthreads();

    // persistent A: rows rg*32..+31 (2 m16 groups), full K (8 k32-steps)
    uint32_t a[2][8][4];
#pragma unroll
    for (int mg = 0; mg < 2; mg++) {
        int row = rg * 32 + mg * 16 + (lane & 7) + ((lane >> 3) & 1) * 8;
#pragma unroll
        for (int ks = 0; ks < 8; ks++) {
            int chunk = 2 * ks + (lane >> 4);
            LDSM4(a[mg][ks], sb + (uint32_t)row * 256 + (uint32_t)((chunk ^ (row & 7)) << 4));
        }
    }

    // per-lane pruning state: 4 row-slots: slot = mg*2 + h -> row rg*32+mg*16+(lane>>2)+h*8
    int rmax[4], mint_l[4];
#pragma unroll
    for (int s = 0; s < 4; s++) {
        int rl = rg * 32 + (s >> 1) * 16 + (lane >> 2) + (s & 1) * 8;
        mint_l[s] = mints[rl];
        rmax[s] = -0x20000000;
    }

    for (int t = 0; t < NT3; t++) {
        MBARRIER_WAIT_PARITY(t & 1 ? bar1 : bar0, (t >> 1) & 1);
        const uint32_t eB = sb + ZQB + (uint32_t)(t & 1) * EB;

        int C[2][8][4];
#pragma unroll
        for (int i = 0; i < 2; i++)
#pragma unroll
            for (int j = 0; j < 8; j++)
#pragma unroll
                for (int k = 0; k < 4; k++) C[i][j][k] = 0;

        // B addresses: this warp's 64 codes = nh*64 + cgb*16 blocks
        uint32_t bbase[4];
        int codesw[4];
#pragma unroll
        for (int cgb = 0; cgb < 4; cgb++) {
            int code = nh * 64 + cgb * 16 + (lane & 7) + ((lane >> 3) & 1) * 8;
            codesw[cgb] = code & 7;
            bbase[cgb] = eB + (uint32_t)code * 256;
        }

        uint32_t b[2][4][4];
#pragma unroll
        for (int cgb = 0; cgb < 4; cgb++) {
            int chunk = 0 + (lane >> 4);
            LDSM4(b[0][cgb], bbase[cgb] + (uint32_t)((chunk ^ codesw[cgb]) << 4));
        }
#pragma unroll
        for (int ks = 0; ks < 8; ks++) {
            const int cur = ks & 1, nxt = cur ^ 1;
            if (ks < 7) {
                int chunk = 2 * (ks + 1) + (lane >> 4);
#pragma unroll
                for (int cgb = 0; cgb < 4; cgb++)
                    LDSM4(b[nxt][cgb], bbase[cgb] + (uint32_t)((chunk ^ codesw[cgb]) << 4));
            }
#pragma unroll
            for (int mg = 0; mg < 2; mg++)
#pragma unroll
                for (int cgb = 0; cgb < 4; cgb++) {
                    imma16832(C[mg][cgb * 2 + 0], a[mg][ks], b[cur][cgb][0], b[cur][cgb][2]);
                    imma16832(C[mg][cgb * 2 + 1], a[mg][ks], b[cur][cgb][1], b[cur][cgb][3]);
                }
        }

        // epilogue: integer capture, exact compares
#pragma unroll
        for (int mg = 0; mg < 2; mg++)
#pragma unroll
            for (int cg = 0; cg < 8; cg++) {
                int kbase = t * TN + nh * 64 + (cg >> 1) * 16 + (cg & 1) * 8 + (lane & 3) * 2;
#pragma unroll
                for (int c = 0; c < 4; c++) {
                    int d = C[mg][cg][c];
                    int s = mg * 2 + (c >> 1);
                    if (d >= rmax[s] - mint_l[s]) {
                        int rl = rg * 32 + (s >> 1) * 16 + (lane >> 2) + (s & 1) * 8;
                        int idx = atomicAdd(&scnt[rl], 1);
                        if (idx < CAP) {
                            g_cand[(size_t)(n0 + rl) * CAP + idx] = kbase + (c & 1);
                            g_cidot[(size_t)(n0 + rl) * CAP + idx] = d;
                        }
                        if (d > rmax[s]) rmax[s] = d;
                    }
                }
            }
        // share running max across the 4 owner lanes
#pragma unroll
        for (int s = 0; s < 4; s++) {
            int m = rmax[s];
            m = max(m, __shfl_xor_sync(0xffffffffu, m, 1));
            m = max(m, __shfl_xor_sync(0xffffffffu, m, 2));
            rmax[s] = m;
        }

        __syncthreads();
        if (tid == 0 && t + 2 < NT3) {
            uint32_t mb = (t & 1) ? bar1 : bar0;
            MBARRIER_EXPECT_TX(mb, EB);
            CPBULK(sb + ZQB + (uint32_t)(t & 1) * EB,
                   (const char*)g_eq + (size_t)(t + 2) * EB, EB, mb);
        }
    }

    // combine thresholds across the two code-half warps
    if ((lane & 3) == 0) {
#pragma unroll
        for (int s = 0; s < 4; s++) {
            int rl = rg * 32 + (s >> 1) * 16 + (lane >> 2) + (s & 1) * 8;
            atomicMax(&thri[rl], rmax[s] - mint_l[s]);
        }
    }
    __syncthreads();
    if (tid < MT) {
        int c = scnt[tid];
        g_cnt[n0 + tid] = c < CAP ? c : CAP;
        g_over[n0 + tid] = (c > CAP) ? 1 : 0;
        g_thri[n0 + tid] = thri[tid];
    }
}

// ---------------- phase 2: exact fp32 rescoring (int-threshold filtered) ----
__global__ void vq_exact(const float* __restrict__ z_e, const float* __restrict__ emb,
                         float* __restrict__ out) {
    __shared__ float zrow[8][DIM];
    int wid = threadIdx.x >> 5, lane = threadIdx.x & 31;
    int row = blockIdx.x * 8 + wid;
    {
        const float4* gz = (const float4*)(z_e + (size_t)row * DIM);
#pragma unroll
        for (int i = 0; i < 2; i++) {
            float4 v = gz[lane + 32 * i];
            *(float4*)&zrow[wid][4 * (lane + 32 * i)] = v;
        }
    }
    __syncwarp();
    const float* zr = zrow[wid];
    float x2 = 0.f;
    for (int d = 0; d < DIM; d++) x2 = __fmaf_rn(zr[d], zr[d], x2);

    float bt = CUDART_INF_F;
    int bk = 0x7fffffff;
    int cnt = g_cnt[row];
    bool over = g_over[row] != 0;
    int thrf = g_thri[row];
    int total = over ? KCODES : cnt;
    for (int c = lane; c < total; c += 32) {
        int k;
        if (over) k = c;
        else {
            if (g_cidot[(size_t)row * CAP + c] < thrf) continue;   // prefix junk
            k = g_cand[(size_t)row * CAP + c];
        }
        const float4* er = (const float4*)(emb + (size_t)k * DIM);
        float dot = 0.f;
#pragma unroll 8
        for (int q = 0; q < DIM / 4; q++) {
            float4 e4 = er[q];
            dot = __fmaf_rn(zr[4 * q + 0], e4.x, dot);
            dot = __fmaf_rn(zr[4 * q + 1], e4.y, dot);
            dot = __fmaf_rn(zr[4 * q + 2], e4.z, dot);
            dot = __fmaf_rn(zr[4 * q + 3], e4.w, dot);
        }
        float S = __fadd_rn(x2, g_e2[k]);
        float tt = __fadd_rn(S, -2.0f * dot);
        if (tt < bt || (tt == bt && k < bk)) { bt = tt; bk = k; }
    }
#pragma unroll
    for (int o = 16; o; o >>= 1) {
        float to = __shfl_down_sync(0xffffffffu, bt, o);
        int ko = __shfl_down_sync(0xffffffffu, bk, o);
        if (to < bt || (to == bt && ko < bk)) { bt = to; bk = ko; }
    }
    bk = __shfl_sync(0xffffffffu, bk, 0);

    // fused gather: z_q_st + loss partial + code output
    const float4* er = (const float4*)(emb + (size_t)bk * DIM);
    float4* po = (float4*)(out + (size_t)row * DIM);
    float sq = 0.f;
#pragma unroll
    for (int j = 0; j < 2; j++) {
        int q = lane + 32 * j;
        float4 e4 = er[q];
        const float* zp = &zrow[wid][4 * q];
        float4 o4;
        float d0 = __fsub_rn(e4.x, zp[0]); o4.x = __fadd_rn(zp[0], d0); sq = __fmaf_rn(d0, d0, sq);
        float d1 = __fsub_rn(e4.y, zp[1]); o4.y = __fadd_rn(zp[1], d1); sq = __fmaf_rn(d1, d1, sq);
        float d2 = __fsub_rn(e4.z, zp[2]); o4.z = __fadd_rn(zp[2], d2); sq = __fmaf_rn(d2, d2, sq);
        float d3 = __fsub_rn(e4.w, zp[3]); o4.w = __fadd_rn(zp[3], d3); sq = __fmaf_rn(d3, d3, sq);
        po[q] = o4;
    }
#pragma unroll
    for (int o = 16; o; o >>= 1) sq += __shfl_down_sync(0xffffffffu, sq, o);
    if (lane == 0) {
        atomicAdd(&g_accum, (double)sq);
        out[(size_t)NROWS * DIM + 1 + row] = (float)bk;
    }
}

__global__ void vq_loss(float* __restrict__ out) {
    float m = (float)(g_accum / (double)((size_t)NROWS * DIM));
    out[(size_t)NROWS * DIM] = __fadd_rn(m, 0.25f * m);
}

// ---------------------------------------------------------------------------
extern "C" void kernel_launch(void* const* d_in, const int* in_sizes, int n_in,
                              void* d_out, int out_size) {
    const float* z_e = (const float*)d_in[0];
    const float* emb = (const float*)d_in[1];
    if (n_in >= 2 && in_sizes[0] == KCODES * DIM && in_sizes[1] == NROWS * DIM) {
        const float* t = z_e; z_e = emb; emb = t;
    }
    float* out = (float*)d_out;

    cudaFuncSetAttribute(vq_mma, cudaFuncAttributeMaxDynamicSharedMemorySize, SMEM_TOT);

    emb_stat_kernel<<<KCODES / 8, 256>>>(emb);
    emb_quant_kernel<<<KCODES * DIM / 4 / 256, 256>>>(emb);
    vq_mma<<<NROWS / MT, 128, SMEM_TOT>>>(z_e);
    vq_exact<<<NROWS / 8, 256>>>(z_e, emb, out);
    vq_loss<<<1, 1>>>(out);
}